// round 15
// baseline (speedup 1.0000x reference)
#include <cuda_runtime.h>
#include <cuda_fp16.h>
#include <math.h>
#include <stdint.h>

#define T 8192
#define D 1024
#define DCND 256
#define NE 8
#define HID 4096
#define CAP 2560
#define NTOK (T*2)
#define ROWS_R (NE*CAP)
#define ROWS_ALL (ROWS_R+T)
#define AD3 3072
#define NCHUNK 64
#define CHUNK 256
#define KC 64                 // K halves per chunk = 128B/row
#define PADH 72               // halves per smem row (64 + 8 pad) = 144B
#define MT_R (CAP/128)        // 20 m-tiles cover capacity-bounded routed experts

// ---------------- scratch (device globals; no allocations) ----------------
__device__ int   g_tope[NTOK];
__device__ float g_topw[NTOK];
__device__ int   g_hist[NCHUNK*NE];
__device__ int   g_coff[NCHUNK*NE];
__device__ int   g_tpe[NE];
__device__ int   g_starts[NE];
__device__ int   g_ne[NE];
__device__ int   g_slot_tok[ROWS_R];
__device__ float g_slot_w[ROWS_R];
__device__ float g_mu[T];
__device__ float g_rstd[T];
__device__ __half g_gate[(size_t)ROWS_ALL*D];    // adaLN gate (fp16)
__device__ __half g_h[(size_t)ROWS_ALL*D];       // modulated LN input (fp16)
__device__ __half g_u[(size_t)ROWS_ALL*HID];     // gelu(h@W1+b1) (fp16)
__device__ __half g_condh[(size_t)T*DCND];       // fp16 cond
// transposed [z][N][K] fp16 weights (Wada column-permuted: pairs (shift_d,scale_d), then gate)
__device__ __half g_wadat[(size_t)(NE+1)*AD3*DCND];
__device__ __half g_w1t[(size_t)(NE+1)*HID*D];
__device__ __half g_w2t[(size_t)(NE+1)*D*HID];

struct P {
  const float *x,*cond,*mask;
  const float *Wada_s,*bada_s,*W1_s,*b1_s,*W2_s,*b2_s;
  const float *Wada_e,*bada_e,*W1_e,*b1_e,*W2_e,*b2_e;
  float *out;
};

// ---------------- helpers ----------------
__device__ __forceinline__ uint32_t s2u(const void* p){
  uint32_t a;
  asm("{ .reg .u64 t; cvta.to.shared.u64 t, %1; cvt.u32.u64 %0, t; }" : "=r"(a) : "l"(p));
  return a;
}
__device__ __forceinline__ void cp16(uint32_t d, const void* s, uint32_t sz){
  asm volatile("cp.async.cg.shared.global [%0], [%1], 16, %2;" :: "r"(d),"l"(s),"r"(sz) : "memory");
}
__device__ __forceinline__ void mma16(float* c, const uint32_t* a, const uint32_t* b){
  asm volatile("mma.sync.aligned.m16n8k16.row.col.f32.f16.f16.f32 "
    "{%0,%1,%2,%3}, {%4,%5,%6,%7}, {%8,%9}, {%0,%1,%2,%3};"
    : "+f"(c[0]),"+f"(c[1]),"+f"(c[2]),"+f"(c[3])
    : "r"(a[0]),"r"(a[1]),"r"(a[2]),"r"(a[3]), "r"(b[0]),"r"(b[1]));
}
__device__ __forceinline__ void ldsm4(uint32_t* r, uint32_t a){
  asm volatile("ldmatrix.sync.aligned.m8n8.x4.shared.b16 {%0,%1,%2,%3}, [%4];"
    : "=r"(r[0]),"=r"(r[1]),"=r"(r[2]),"=r"(r[3]) : "r"(a));
}
__device__ __forceinline__ void red2(float* a, float v0, float v1){
  asm volatile("red.global.add.v2.f32 [%0], {%1, %2};" :: "l"(a), "f"(v0), "f"(v1) : "memory");
}

// ---------------- f32 -> f16 copy (cond) ----------------
__global__ void k_tohalf(const float* __restrict__ s, __half* __restrict__ d, size_t n4){
  size_t i=(size_t)blockIdx.x*blockDim.x+threadIdx.x;
  if(i>=n4) return;
  float4 v=((const float4*)s)[i];
  __half2 lo=__floats2half2_rn(v.x,v.y);
  __half2 hi=__floats2half2_rn(v.z,v.w);
  uint2 o; o.x=*(uint32_t*)&lo; o.y=*(uint32_t*)&hi;
  ((uint2*)d)[i]=o;
}

// ---------------- weight transpose [K,N]->[N,K] fp16, 64x64 tiles ----------------
template<int MODE>
__global__ void k_wt(P p){
  constexpr int KD=(MODE==0)?DCND:(MODE==1)?D:HID;
  constexpr int ND=(MODE==0)?AD3:(MODE==1)?HID:D;
  int z=blockIdx.z;
  const float* W;
  if(MODE==0) W=(z<NE)? p.Wada_e+(size_t)z*KD*ND : p.Wada_s;
  else if(MODE==1) W=(z<NE)? p.W1_e+(size_t)z*KD*ND : p.W1_s;
  else W=(z<NE)? p.W2_e+(size_t)z*KD*ND : p.W2_s;
  __half* Wt=((MODE==0)? g_wadat : (MODE==1)? g_w1t : g_w2t)+(size_t)z*KD*ND;
  __shared__ float t[64][65];
  int n0=blockIdx.x*64, k0=blockIdx.y*64;
  int tx=threadIdx.x, ty=threadIdx.y;        // tx 0..63, ty 0..3
  int n=n0+tx;
  int srcn=n;
  if(MODE==0 && n<2*D) srcn=(n&1)? D+(n>>1) : (n>>1);   // interleave shift/scale
  #pragma unroll
  for(int r=0;r<16;r++){
    int kr=ty+4*r;
    t[kr][tx]=W[(size_t)(k0+kr)*ND+srcn];
  }
  __syncthreads();
  #pragma unroll
  for(int r=0;r<16;r++){
    int nr=ty+4*r;
    Wt[(size_t)(n0+nr)*KD+k0+tx]=__float2half_rn(t[tx][nr]);
  }
}

// ---------------- router + LN stats fused: warp/token ----------------
__global__ void k_router(const float* __restrict__ x, const float* __restrict__ Wg){
  int w=(blockIdx.x*blockDim.x+threadIdx.x)>>5;
  int lane=threadIdx.x&31;
  if(w>=T) return;
  const float* xr=x+(size_t)w*D;
  float a[7]={0.f,0.f,0.f,0.f,0.f,0.f,0.f};
  float s=0.f,s2=0.f;
  for(int k=lane;k<D;k+=32){
    float xv=xr[k];
    s+=xv; s2+=xv*xv;
    #pragma unroll
    for(int j=0;j<7;j++) a[j]+=xv*Wg[k*7+j];
  }
  #pragma unroll
  for(int j=0;j<7;j++)
    for(int o=16;o;o>>=1) a[j]+=__shfl_xor_sync(0xffffffffu,a[j],o);
  for(int o=16;o;o>>=1){
    s+=__shfl_xor_sync(0xffffffffu,s,o);
    s2+=__shfl_xor_sync(0xffffffffu,s2,o);
  }
  if(lane==0){
    int j0=0;
    #pragma unroll
    for(int j=1;j<7;j++) if(a[j]>a[j0]) j0=j;
    int j1=-1;
    #pragma unroll
    for(int j=0;j<7;j++){ if(j==j0) continue; if(j1<0||a[j]>a[j1]) j1=j; }
    float e1=expf(a[j1]-a[j0]);
    float inv=1.f/(1.f+e1);
    g_tope[2*w]=j0;   g_topw[2*w]=inv;
    g_tope[2*w+1]=j1; g_topw[2*w+1]=e1*inv;
    float mu=s*(1.f/(float)D);
    float var=s2*(1.f/(float)D)-mu*mu;
    g_mu[w]=mu;
    g_rstd[w]=rsqrtf(var+1e-5f);
  }
}

// ---------------- stable counting sort by expert ----------------
__global__ void k_hist(){
  __shared__ int cnt[NE];
  int tid=threadIdx.x;
  if(tid<NE) cnt[tid]=0;
  __syncthreads();
  atomicAdd(&cnt[g_tope[blockIdx.x*CHUNK+tid]],1);
  __syncthreads();
  if(tid<NE) g_hist[blockIdx.x*NE+tid]=cnt[tid];
}
__global__ void k_scan(){
  int tid=threadIdx.x;
  __shared__ int tpe[NE], st[NE];
  if(tid<NE){
    int s=0;
    for(int c=0;c<NCHUNK;c++) s+=g_hist[c*NE+tid];
    tpe[tid]=s; g_tpe[tid]=s; g_ne[tid]=s<CAP?s:CAP;
  }
  __syncthreads();
  if(tid==0){
    int cum=0;
    for(int e=0;e<NE;e++){ st[e]=cum; g_starts[e]=cum; cum+=tpe[e]; }
  }
  __syncthreads();
  if(tid<NE){
    int run=st[tid];
    for(int c=0;c<NCHUNK;c++){ g_coff[c*NE+tid]=run; run+=g_hist[c*NE+tid]; }
  }
}
__global__ void k_place(){
  __shared__ int se[CHUNK];
  int tid=threadIdx.x;
  int g=blockIdx.x*CHUNK+tid;
  int e=g_tope[g];
  se[tid]=e;
  __syncthreads();
  int rank=0;
  for(int j=0;j<tid;j++) rank += (se[j]==e);
  int pos=g_coff[blockIdx.x*NE+e]+rank;
  int slot=pos-g_starts[e];
  if(slot<CAP){
    g_slot_tok[e*CAP+slot]=g>>1;
    g_slot_w[e*CAP+slot]=g_topw[g];
  }
}

// fast gelu-tanh: tanh(y) = 1 - 2/(1+e^{2y}) via ex2.approx + rcp.approx (~1e-6 rel err)
__device__ __forceinline__ float gelu_tanh(float v){
  const float c=0.7978845608028654f;
  float y=c*(v+0.044715f*v*v*v);
  float e; asm("ex2.approx.f32 %0, %1;" : "=f"(e) : "f"(2.885390081777927f*y));
  float r; asm("rcp.approx.f32 %0, %1;" : "=f"(r) : "f"(e+1.f));
  float th=1.f-2.f*r;
  return 0.5f*v*(1.f+th);
}

// ---------------- fp16 mma.sync GEMM, 128x128 tile, 256 thr, 3-stage cp.async ----------------
// MODE 0: ada(permuted) -> fused LN-modulate epilogue -> g_h, g_gate
// MODE 1: u = f16(gelu(g_h @ W1 + b1))
// MODE 2: y -> routed: gate*mask*w*2/3 red.v2 out
// MODE 3: y -> shared: gate*mask*1/3 STORE out
template<int MODE>
__global__ void __launch_bounds__(256,2) k_gemm_mma(P p, int z0, int y0){
  constexpr int KD=(MODE==0)?DCND:(MODE==1)?D:HID;
  constexpr int ND=(MODE==0)?AD3:(MODE==1)?HID:D;
  constexpr int NC=KD/KC;
  constexpr uint32_t BUF=128*PADH*2;    // 18432 B per stage per operand

  int z=blockIdx.z+z0;
  int Mz=(z<NE)? g_ne[z] : T;
  int m0=(blockIdx.y+y0)*128;
  if(m0>=Mz) return;
  int n0=blockIdx.x*128;
  int base=(z<NE)? z*CAP : ROWS_R;

  extern __shared__ __half smh[];
  uint32_t sa=s2u(smh);        // A: 3 stages
  uint32_t sb=sa+3*BUF;        // B: 3 stages

  int tid=threadIdx.x, warp=tid>>5, lane=tid&31;
  int wm=warp>>1, wn=warp&1;
  int g4=lane>>2, t4=lane&3;
  int tsel=lane>>3, tr=lane&7;

  const __half* Wt=((MODE==0)? g_wadat : (MODE==1)? g_w1t : g_w2t)+(size_t)z*(size_t)KD*ND;
  const float* bias;
  if(MODE==0) bias=(z<NE)? p.bada_e+z*AD3 : p.bada_s;
  else if(MODE==1) bias=(z<NE)? p.b1_e+z*HID : p.b1_s;
  else bias=(z<NE)? p.b2_e+z*D : p.b2_s;

  // loaders: thread owns row (tid>>1), half-row segment (tid&1)
  int lrow=tid>>1, lseg=tid&1;
  const __half* pA;
  uint32_t asz=16;
  if(MODE==0){
    int tok=(z<NE)? g_slot_tok[z*CAP+m0+lrow] : (m0+lrow);
    if(tok<0){ tok=0; asz=0; }
    pA=g_condh+(size_t)tok*DCND+lseg*32;
  } else {
    const __half* Ab=(MODE==1)? g_h : g_u;
    pA=Ab+(size_t)(base+m0+lrow)*KD+lseg*32;
  }
  const __half* pB=Wt+(size_t)(n0+lrow)*KD+lseg*32;

  uint32_t da0=sa+(uint32_t)(lrow*PADH+lseg*32)*2;
  uint32_t db0=sb+(uint32_t)(lrow*PADH+lseg*32)*2;

  uint32_t abase=sa+(uint32_t)(((wm*32+(tsel&1)*8+tr)*PADH+(tsel>>1)*8)*2);
  uint32_t bbase=sb+(uint32_t)(((wn*64+(tsel>>1)*8+tr)*PADH+(tsel&1)*8)*2);

  float acc[2][8][4];
  #pragma unroll
  for(int mt=0;mt<2;mt++)
    #pragma unroll
    for(int nt=0;nt<8;nt++)
      #pragma unroll
      for(int r=0;r<4;r++) acc[mt][nt][r]=0.f;

  auto issue=[&](int c,int buf){
    uint32_t da=da0+buf*BUF;
    const __half* srcA=pA+(size_t)c*KC;
    #pragma unroll
    for(int i=0;i<4;i++) cp16(da+i*16, srcA+i*8, asz);
    uint32_t db=db0+buf*BUF;
    const __half* srcB=pB+(size_t)c*KC;
    #pragma unroll
    for(int i=0;i<4;i++) cp16(db+i*16, srcB+i*8, 16u);
    asm volatile("cp.async.commit_group;" ::: "memory");
  };

  issue(0,0);
  if(NC>1) issue(1,1);
  int buf=0;
  for(int c=0;c<NC;c++){
    if(c+1<NC) asm volatile("cp.async.wait_group 1;" ::: "memory");
    else       asm volatile("cp.async.wait_group 0;" ::: "memory");
    __syncthreads();
    uint32_t ao=abase+buf*BUF;
    uint32_t bo=bbase+buf*BUF;
    #pragma unroll
    for(int kk=0;kk<4;kk++){                 // 4 x K16 per chunk
      uint32_t af[2][4], bf[4][4];
      #pragma unroll
      for(int mt=0;mt<2;mt++) ldsm4(af[mt], ao+(uint32_t)((mt*16*PADH)*2+kk*32));
      #pragma unroll
      for(int np=0;np<4;np++) ldsm4(bf[np], bo+(uint32_t)((np*16*PADH)*2+kk*32));
      #pragma unroll
      for(int mt=0;mt<2;mt++)
        #pragma unroll
        for(int np=0;np<4;np++){
          mma16(acc[mt][2*np+0], af[mt], &bf[np][0]);
          mma16(acc[mt][2*np+1], af[mt], &bf[np][2]);
        }
    }
    if(c+2<NC){
      int nb=buf+2; if(nb>=3) nb-=3;
      issue(c+2,nb);
    }
    if(++buf==3) buf=0;
  }

  // ---- epilogue ----
  #pragma unroll
  for(int mt=0;mt<2;mt++){
    int r0=m0+wm*32+mt*16+g4;
    #pragma unroll
    for(int half=0;half<2;half++){
      int r=r0+half*8;
      if(MODE==0){
        int tok; bool valid=true;
        if(z<NE){ tok=g_slot_tok[z*CAP+r]; valid=(tok>=0); }
        else tok=r;
        float mu=0.f, rs=0.f;
        if(valid){ mu=g_mu[tok]; rs=g_rstd[tok]; }
        int strip=n0+wn*64;
        if(strip<2*D){
          __half* hp=g_h+(size_t)(base+r)*D;
          #pragma unroll
          for(int nt=0;nt<8;nt++){
            int d=(strip+nt*8+t4*2)>>1;
            float hv=0.f;
            if(valid){
              float sh=acc[mt][nt][half*2+0]+bias[d];
              float sc=acc[mt][nt][half*2+1]+bias[D+d];
              float xv=p.x[(size_t)tok*D+d];
              hv=(xv-mu)*rs*(1.f+sc)+sh;
            }
            hp[d]=__float2half_rn(hv);
          }
        } else {
          __half* gp=g_gate+(size_t)(base+r)*D;
          #pragma unroll
          for(int nt=0;nt<8;nt++){
            int d0=strip+nt*8+t4*2-2*D;
            float gv0=0.f, gv1=0.f;
            if(valid){
              gv0=acc[mt][nt][half*2+0]+bias[2*D+d0];
              gv1=acc[mt][nt][half*2+1]+bias[2*D+d0+1];
            }
            __half2 hv=__floats2half2_rn(gv0,gv1);
            *(uint32_t*)(gp+d0)=*(uint32_t*)&hv;
          }
        }
      } else if(MODE==1){
        size_t ro=(size_t)(base+r)*ND;
        #pragma unroll
        for(int nt=0;nt<8;nt++){
          int col=n0+wn*64+nt*8+t4*2;
          float v0=gelu_tanh(acc[mt][nt][half*2+0]+bias[col+0]);
          float v1=gelu_tanh(acc[mt][nt][half*2+1]+bias[col+1]);
          __half2 hv=__floats2half2_rn(v0,v1);
          *(uint32_t*)(g_u+ro+col)=*(uint32_t*)&hv;
        }
      } else if(MODE==2){
        const __half* gp=g_gate+(size_t)(base+r)*D;
        int sidx=z*CAP+r;
        int tok=g_slot_tok[sidx];
        if(tok<0) continue;
        float f=g_slot_w[sidx]*p.mask[tok]*(2.f/3.f);
        float* op=p.out+(size_t)tok*D;
        #pragma unroll
        for(int nt=0;nt<8;nt++){
          int col=n0+wn*64+nt*8+t4*2;
          uint32_t gu=*(const uint32_t*)(gp+col);
          float2 gv=__half22float2(*(__half2*)&gu);
          red2(&op[col],
               (acc[mt][nt][half*2+0]+bias[col+0])*gv.x*f,
               (acc[mt][nt][half*2+1]+bias[col+1])*gv.y*f);
        }
      } else {
        // MODE 3: shared-expert store (initializes out)
        const __half* gp=g_gate+(size_t)(base+r)*D;
        float f=p.mask[r]*(1.f/3.f);
        float* op=p.out+(size_t)r*D;
        #pragma unroll
        for(int nt=0;nt<8;nt++){
          int col=n0+wn*64+nt*8+t4*2;
          uint32_t gu=*(const uint32_t*)(gp+col);
          float2 gv=__half22float2(*(__half2*)&gu);
          float2 o;
          o.x=(acc[mt][nt][half*2+0]+bias[col+0])*gv.x*f;
          o.y=(acc[mt][nt][half*2+1]+bias[col+1])*gv.y*f;
          *(float2*)(op+col)=o;
        }
      }
    }
  }
}

extern "C" void kernel_launch(void* const* d_in, const int* in_sizes, int n_in,
                              void* d_out, int out_size){
  P p;
  p.x     =(const float*)d_in[0];
  p.cond  =(const float*)d_in[1];
  p.mask  =(const float*)d_in[2];
  const float* Wg=(const float*)d_in[3];
  p.Wada_s=(const float*)d_in[4];
  p.bada_s=(const float*)d_in[5];
  p.W1_s  =(const float*)d_in[6];
  p.b1_s  =(const float*)d_in[7];
  p.W2_s  =(const float*)d_in[8];
  p.b2_s  =(const float*)d_in[9];
  p.Wada_e=(const float*)d_in[10];
  p.bada_e=(const float*)d_in[11];
  p.W1_e  =(const float*)d_in[12];
  p.b1_e  =(const float*)d_in[13];
  p.W2_e  =(const float*)d_in[14];
  p.b2_e  =(const float*)d_in[15];
  p.out   =(float*)d_out;

  const int SMEM_SZ=6*128*PADH*2;   // 110592 B
  cudaFuncSetAttribute(k_gemm_mma<0>, cudaFuncAttributeMaxDynamicSharedMemorySize, SMEM_SZ);
  cudaFuncSetAttribute(k_gemm_mma<1>, cudaFuncAttributeMaxDynamicSharedMemorySize, SMEM_SZ);
  cudaFuncSetAttribute(k_gemm_mma<2>, cudaFuncAttributeMaxDynamicSharedMemorySize, SMEM_SZ);
  cudaFuncSetAttribute(k_gemm_mma<3>, cudaFuncAttributeMaxDynamicSharedMemorySize, SMEM_SZ);

  // lazily-created side streams/events (host resources only; work is identical each call)
  static cudaStream_t sA=nullptr, sB=nullptr;
  static cudaEvent_t evFork=nullptr, ev1=nullptr, ev2=nullptr;
  static cudaEvent_t evWt0=nullptr, evR=nullptr, evM2s=nullptr, evEnd=nullptr;
  if(!sA){
    cudaStreamCreateWithFlags(&sA, cudaStreamNonBlocking);
    cudaStreamCreateWithFlags(&sB, cudaStreamNonBlocking);
    cudaEventCreateWithFlags(&evFork, cudaEventDisableTiming);
    cudaEventCreateWithFlags(&ev1,    cudaEventDisableTiming);
    cudaEventCreateWithFlags(&ev2,    cudaEventDisableTiming);
    cudaEventCreateWithFlags(&evWt0,  cudaEventDisableTiming);
    cudaEventCreateWithFlags(&evR,    cudaEventDisableTiming);
    cudaEventCreateWithFlags(&evM2s,  cudaEventDisableTiming);
    cudaEventCreateWithFlags(&evEnd,  cudaEventDisableTiming);
  }

  void *pslot=nullptr, *pch=nullptr;
  cudaGetSymbolAddress(&pslot, g_slot_tok);
  cudaGetSymbolAddress(&pch,   g_condh);

  // fork side streams off the origin (capture) stream
  cudaEventRecord(evFork, 0);
  cudaStreamWaitEvent(sA, evFork, 0);
  cudaStreamWaitEvent(sB, evFork, 0);

  // stream A: big weight transposes (consumed by both chains)
  {
    dim3 b(64,4);
    dim3 g1(HID/64, D/64,   NE+1);  k_wt<1><<<g1,b,0,sA>>>(p);
    cudaEventRecord(ev1, sA);
    dim3 g2(D/64,   HID/64, NE+1);  k_wt<2><<<g2,b,0,sA>>>(p);
    cudaEventRecord(ev2, sA);
  }

  // stream B: ROUTED chain prep (router first → evR for shared chain's LN stats)
  {
    cudaMemsetAsync(pslot, 0xFF, sizeof(int)*ROWS_R, sB);
    k_router <<<T/4, 128, 0, sB>>>(p.x, Wg);     // fused router + LN stats
    cudaEventRecord(evR, sB);                     // g_mu/g_rstd ready
    k_hist   <<<NCHUNK, CHUNK, 0, sB>>>();
    k_scan   <<<1, 32, 0, sB>>>();
    k_place  <<<NCHUNK, CHUNK, 0, sB>>>();
  }

  // origin stream: SHARED chain (M1/M3 interleaved in half-T chunks for L2 reuse of g_u)
  {
    size_t n4=(size_t)T*DCND/4;
    k_tohalf<<<(unsigned)((n4+255)/256),256>>>(p.cond,(__half*)pch,n4);
    dim3 b(64,4);
    dim3 ga(AD3/64, DCND/64, NE+1); k_wt<0><<<ga,b>>>(p);
    cudaEventRecord(evWt0, 0);
  }
  cudaStreamWaitEvent(0, evR, 0);               // shared M0 needs g_mu/g_rstd
  dim3 g0s(AD3/128, T/128, 1);   k_gemm_mma<0><<<g0s, 256, SMEM_SZ>>>(p, NE, 0);
  cudaStreamWaitEvent(0, ev1, 0);
  cudaStreamWaitEvent(0, ev2, 0);
  dim3 g1h(HID/128, T/256, 1);   // half-T M1 chunks
  dim3 g3h(D/128,   T/256, 1);   // half-T M3 chunks
  k_gemm_mma<1><<<g1h, 256, SMEM_SZ>>>(p, NE, 0);
  k_gemm_mma<3><<<g3h, 256, SMEM_SZ>>>(p, NE, 0);
  k_gemm_mma<1><<<g1h, 256, SMEM_SZ>>>(p, NE, T/256);
  k_gemm_mma<3><<<g3h, 256, SMEM_SZ>>>(p, NE, T/256);
  cudaEventRecord(evM2s, 0);

  // stream B: ROUTED chain GEMMs; M1/M2 interleaved per expert-pair for L2 reuse of g_u
  cudaStreamWaitEvent(sB, evWt0, 0);
  dim3 g0r(AD3/128, MT_R, NE); k_gemm_mma<0><<<g0r, 256, SMEM_SZ, sB>>>(p, 0, 0);
  cudaStreamWaitEvent(sB, ev1, 0);
  cudaStreamWaitEvent(sB, ev2, 0);
  cudaStreamWaitEvent(sB, evM2s, 0);            // red ops must follow shared stores
  dim3 g1p(HID/128, MT_R, 2);
  dim3 g2p(D/128,   MT_R, 2);
  for(int zp=0; zp<NE; zp+=2){
    k_gemm_mma<1><<<g1p, 256, SMEM_SZ, sB>>>(p, zp, 0);
    k_gemm_mma<2><<<g2p, 256, SMEM_SZ, sB>>>(p, zp, 0);
  }
  cudaEventRecord(evEnd, sB);

  // join routed chain back into origin
  cudaStreamWaitEvent(0, evEnd, 0);
}

// round 16
// speedup vs baseline: 1.0831x; 1.0831x over previous
#include <cuda_runtime.h>
#include <cuda_fp16.h>
#include <math.h>
#include <stdint.h>

#define T 8192
#define D 1024
#define DCND 256
#define NE 8
#define HID 4096
#define CAP 2560
#define NTOK (T*2)
#define ROWS_R (NE*CAP)
#define ROWS_ALL (ROWS_R+T)
#define AD3 3072
#define NCHUNK 64
#define CHUNK 256
#define KC 64                 // K halves per chunk = 128B/row
#define PADH 72               // halves per smem row (64 + 8 pad) = 144B
#define MT_R (CAP/128)        // 20 m-tiles cover capacity-bounded routed experts

// ---------------- scratch (device globals; no allocations) ----------------
__device__ int   g_tope[NTOK];
__device__ float g_topw[NTOK];
__device__ int   g_hist[NCHUNK*NE];
__device__ int   g_coff[NCHUNK*NE];
__device__ int   g_tpe[NE];
__device__ int   g_starts[NE];
__device__ int   g_ne[NE];
__device__ int   g_slot_tok[ROWS_R];
__device__ float g_slot_w[ROWS_R];
__device__ float g_mu[T];
__device__ float g_rstd[T];
__device__ __half g_gate[(size_t)ROWS_ALL*D];    // adaLN gate (fp16)
__device__ __half g_h[(size_t)ROWS_ALL*D];       // modulated LN input (fp16)
__device__ __half g_u[(size_t)ROWS_ALL*HID];     // gelu(h@W1+b1) (fp16)
__device__ __half g_condh[(size_t)T*DCND];       // fp16 cond
// transposed [z][N][K] fp16 weights (Wada column-permuted: pairs (shift_d,scale_d), then gate)
__device__ __half g_wadat[(size_t)(NE+1)*AD3*DCND];
__device__ __half g_w1t[(size_t)(NE+1)*HID*D];
__device__ __half g_w2t[(size_t)(NE+1)*D*HID];

struct P {
  const float *x,*cond,*mask;
  const float *Wada_s,*bada_s,*W1_s,*b1_s,*W2_s,*b2_s;
  const float *Wada_e,*bada_e,*W1_e,*b1_e,*W2_e,*b2_e;
  float *out;
};

// ---------------- helpers ----------------
__device__ __forceinline__ uint32_t s2u(const void* p){
  uint32_t a;
  asm("{ .reg .u64 t; cvta.to.shared.u64 t, %1; cvt.u32.u64 %0, t; }" : "=r"(a) : "l"(p));
  return a;
}
__device__ __forceinline__ void cp16(uint32_t d, const void* s, uint32_t sz){
  asm volatile("cp.async.cg.shared.global [%0], [%1], 16, %2;" :: "r"(d),"l"(s),"r"(sz) : "memory");
}
__device__ __forceinline__ void mma16(float* c, const uint32_t* a, const uint32_t* b){
  asm volatile("mma.sync.aligned.m16n8k16.row.col.f32.f16.f16.f32 "
    "{%0,%1,%2,%3}, {%4,%5,%6,%7}, {%8,%9}, {%0,%1,%2,%3};"
    : "+f"(c[0]),"+f"(c[1]),"+f"(c[2]),"+f"(c[3])
    : "r"(a[0]),"r"(a[1]),"r"(a[2]),"r"(a[3]), "r"(b[0]),"r"(b[1]));
}
__device__ __forceinline__ void ldsm4(uint32_t* r, uint32_t a){
  asm volatile("ldmatrix.sync.aligned.m8n8.x4.shared.b16 {%0,%1,%2,%3}, [%4];"
    : "=r"(r[0]),"=r"(r[1]),"=r"(r[2]),"=r"(r[3]) : "r"(a));
}
__device__ __forceinline__ void red2(float* a, float v0, float v1){
  asm volatile("red.global.add.v2.f32 [%0], {%1, %2};" :: "l"(a), "f"(v0), "f"(v1) : "memory");
}

// ---------------- f32 -> f16 copy (cond) ----------------
__global__ void k_tohalf(const float* __restrict__ s, __half* __restrict__ d, size_t n4){
  size_t i=(size_t)blockIdx.x*blockDim.x+threadIdx.x;
  if(i>=n4) return;
  float4 v=((const float4*)s)[i];
  __half2 lo=__floats2half2_rn(v.x,v.y);
  __half2 hi=__floats2half2_rn(v.z,v.w);
  uint2 o; o.x=*(uint32_t*)&lo; o.y=*(uint32_t*)&hi;
  ((uint2*)d)[i]=o;
}

// ---------------- weight transpose [K,N]->[N,K] fp16, 64x64 tiles ----------------
template<int MODE>
__global__ void k_wt(P p){
  constexpr int KD=(MODE==0)?DCND:(MODE==1)?D:HID;
  constexpr int ND=(MODE==0)?AD3:(MODE==1)?HID:D;
  int z=blockIdx.z;
  const float* W;
  if(MODE==0) W=(z<NE)? p.Wada_e+(size_t)z*KD*ND : p.Wada_s;
  else if(MODE==1) W=(z<NE)? p.W1_e+(size_t)z*KD*ND : p.W1_s;
  else W=(z<NE)? p.W2_e+(size_t)z*KD*ND : p.W2_s;
  __half* Wt=((MODE==0)? g_wadat : (MODE==1)? g_w1t : g_w2t)+(size_t)z*KD*ND;
  __shared__ float t[64][65];
  int n0=blockIdx.x*64, k0=blockIdx.y*64;
  int tx=threadIdx.x, ty=threadIdx.y;        // tx 0..63, ty 0..3
  int n=n0+tx;
  int srcn=n;
  if(MODE==0 && n<2*D) srcn=(n&1)? D+(n>>1) : (n>>1);   // interleave shift/scale
  #pragma unroll
  for(int r=0;r<16;r++){
    int kr=ty+4*r;
    t[kr][tx]=W[(size_t)(k0+kr)*ND+srcn];
  }
  __syncthreads();
  #pragma unroll
  for(int r=0;r<16;r++){
    int nr=ty+4*r;
    Wt[(size_t)(n0+nr)*KD+k0+tx]=__float2half_rn(t[tx][nr]);
  }
}

// ---------------- router + LN stats fused: warp/token ----------------
__global__ void k_router(const float* __restrict__ x, const float* __restrict__ Wg){
  int w=(blockIdx.x*blockDim.x+threadIdx.x)>>5;
  int lane=threadIdx.x&31;
  if(w>=T) return;
  const float* xr=x+(size_t)w*D;
  float a[7]={0.f,0.f,0.f,0.f,0.f,0.f,0.f};
  float s=0.f,s2=0.f;
  for(int k=lane;k<D;k+=32){
    float xv=xr[k];
    s+=xv; s2+=xv*xv;
    #pragma unroll
    for(int j=0;j<7;j++) a[j]+=xv*Wg[k*7+j];
  }
  #pragma unroll
  for(int j=0;j<7;j++)
    for(int o=16;o;o>>=1) a[j]+=__shfl_xor_sync(0xffffffffu,a[j],o);
  for(int o=16;o;o>>=1){
    s+=__shfl_xor_sync(0xffffffffu,s,o);
    s2+=__shfl_xor_sync(0xffffffffu,s2,o);
  }
  if(lane==0){
    int j0=0;
    #pragma unroll
    for(int j=1;j<7;j++) if(a[j]>a[j0]) j0=j;
    int j1=-1;
    #pragma unroll
    for(int j=0;j<7;j++){ if(j==j0) continue; if(j1<0||a[j]>a[j1]) j1=j; }
    float e1=expf(a[j1]-a[j0]);
    float inv=1.f/(1.f+e1);
    g_tope[2*w]=j0;   g_topw[2*w]=inv;
    g_tope[2*w+1]=j1; g_topw[2*w+1]=e1*inv;
    float mu=s*(1.f/(float)D);
    float var=s2*(1.f/(float)D)-mu*mu;
    g_mu[w]=mu;
    g_rstd[w]=rsqrtf(var+1e-5f);
  }
}

// ---------------- stable counting sort by expert ----------------
__global__ void k_hist(){
  __shared__ int cnt[NE];
  int tid=threadIdx.x;
  if(tid<NE) cnt[tid]=0;
  __syncthreads();
  atomicAdd(&cnt[g_tope[blockIdx.x*CHUNK+tid]],1);
  __syncthreads();
  if(tid<NE) g_hist[blockIdx.x*NE+tid]=cnt[tid];
}
__global__ void k_scan(){
  int tid=threadIdx.x;
  __shared__ int tpe[NE], st[NE];
  if(tid<NE){
    int s=0;
    for(int c=0;c<NCHUNK;c++) s+=g_hist[c*NE+tid];
    tpe[tid]=s; g_tpe[tid]=s; g_ne[tid]=s<CAP?s:CAP;
  }
  __syncthreads();
  if(tid==0){
    int cum=0;
    for(int e=0;e<NE;e++){ st[e]=cum; g_starts[e]=cum; cum+=tpe[e]; }
  }
  __syncthreads();
  if(tid<NE){
    int run=st[tid];
    for(int c=0;c<NCHUNK;c++){ g_coff[c*NE+tid]=run; run+=g_hist[c*NE+tid]; }
  }
}
__global__ void k_place(){
  __shared__ int se[CHUNK];
  int tid=threadIdx.x;
  int g=blockIdx.x*CHUNK+tid;
  int e=g_tope[g];
  se[tid]=e;
  __syncthreads();
  int rank=0;
  for(int j=0;j<tid;j++) rank += (se[j]==e);
  int pos=g_coff[blockIdx.x*NE+e]+rank;
  int slot=pos-g_starts[e];
  if(slot<CAP){
    g_slot_tok[e*CAP+slot]=g>>1;
    g_slot_w[e*CAP+slot]=g_topw[g];
  }
}

// fast gelu-tanh: tanh(y) = 1 - 2/(1+e^{2y}) via ex2.approx + rcp.approx (~1e-6 rel err)
__device__ __forceinline__ float gelu_tanh(float v){
  const float c=0.7978845608028654f;
  float y=c*(v+0.044715f*v*v*v);
  float e; asm("ex2.approx.f32 %0, %1;" : "=f"(e) : "f"(2.885390081777927f*y));
  float r; asm("rcp.approx.f32 %0, %1;" : "=f"(r) : "f"(e+1.f));
  float th=1.f-2.f*r;
  return 0.5f*v*(1.f+th);
}

// ---------------- fp16 mma.sync GEMM, 128x128 tile, 256 thr, 3-stage cp.async ----------------
// MODE 0: ada(permuted) -> fused LN-modulate epilogue -> g_h, g_gate
// MODE 1: u = f16(gelu(g_h @ W1 + b1))
// MODE 2: y -> routed: gate*mask*w*2/3 red.v2 out
// MODE 3: y -> shared: gate*mask*1/3 STORE out
template<int MODE>
__global__ void __launch_bounds__(256,2) k_gemm_mma(P p, int z0){
  constexpr int KD=(MODE==0)?DCND:(MODE==1)?D:HID;
  constexpr int ND=(MODE==0)?AD3:(MODE==1)?HID:D;
  constexpr int NC=KD/KC;
  constexpr uint32_t BUF=128*PADH*2;    // 18432 B per stage per operand

  int z=blockIdx.z+z0;
  int Mz=(z<NE)? g_ne[z] : T;
  int m0=blockIdx.y*128;
  if(m0>=Mz) return;
  int n0=blockIdx.x*128;
  int base=(z<NE)? z*CAP : ROWS_R;

  extern __shared__ __half smh[];
  uint32_t sa=s2u(smh);        // A: 3 stages
  uint32_t sb=sa+3*BUF;        // B: 3 stages

  int tid=threadIdx.x, warp=tid>>5, lane=tid&31;
  int wm=warp>>1, wn=warp&1;
  int g4=lane>>2, t4=lane&3;
  int tsel=lane>>3, tr=lane&7;

  const __half* Wt=((MODE==0)? g_wadat : (MODE==1)? g_w1t : g_w2t)+(size_t)z*(size_t)KD*ND;
  const float* bias;
  if(MODE==0) bias=(z<NE)? p.bada_e+z*AD3 : p.bada_s;
  else if(MODE==1) bias=(z<NE)? p.b1_e+z*HID : p.b1_s;
  else bias=(z<NE)? p.b2_e+z*D : p.b2_s;

  // loaders: thread owns row (tid>>1), half-row segment (tid&1)
  int lrow=tid>>1, lseg=tid&1;
  const __half* pA;
  uint32_t asz=16;
  if(MODE==0){
    int tok=(z<NE)? g_slot_tok[z*CAP+m0+lrow] : (m0+lrow);
    if(tok<0){ tok=0; asz=0; }
    pA=g_condh+(size_t)tok*DCND+lseg*32;
  } else {
    const __half* Ab=(MODE==1)? g_h : g_u;
    pA=Ab+(size_t)(base+m0+lrow)*KD+lseg*32;
  }
  const __half* pB=Wt+(size_t)(n0+lrow)*KD+lseg*32;

  uint32_t da0=sa+(uint32_t)(lrow*PADH+lseg*32)*2;
  uint32_t db0=sb+(uint32_t)(lrow*PADH+lseg*32)*2;

  uint32_t abase=sa+(uint32_t)(((wm*32+(tsel&1)*8+tr)*PADH+(tsel>>1)*8)*2);
  uint32_t bbase=sb+(uint32_t)(((wn*64+(tsel>>1)*8+tr)*PADH+(tsel&1)*8)*2);

  float acc[2][8][4];
  #pragma unroll
  for(int mt=0;mt<2;mt++)
    #pragma unroll
    for(int nt=0;nt<8;nt++)
      #pragma unroll
      for(int r=0;r<4;r++) acc[mt][nt][r]=0.f;

  auto issue=[&](int c,int buf){
    uint32_t da=da0+buf*BUF;
    const __half* srcA=pA+(size_t)c*KC;
    #pragma unroll
    for(int i=0;i<4;i++) cp16(da+i*16, srcA+i*8, asz);
    uint32_t db=db0+buf*BUF;
    const __half* srcB=pB+(size_t)c*KC;
    #pragma unroll
    for(int i=0;i<4;i++) cp16(db+i*16, srcB+i*8, 16u);
    asm volatile("cp.async.commit_group;" ::: "memory");
  };

  issue(0,0);
  if(NC>1) issue(1,1);
  int buf=0;
  for(int c=0;c<NC;c++){
    if(c+1<NC) asm volatile("cp.async.wait_group 1;" ::: "memory");
    else       asm volatile("cp.async.wait_group 0;" ::: "memory");
    __syncthreads();
    uint32_t ao=abase+buf*BUF;
    uint32_t bo=bbase+buf*BUF;
    #pragma unroll
    for(int kk=0;kk<4;kk++){                 // 4 x K16 per chunk
      uint32_t af[2][4], bf[4][4];
      #pragma unroll
      for(int mt=0;mt<2;mt++) ldsm4(af[mt], ao+(uint32_t)((mt*16*PADH)*2+kk*32));
      #pragma unroll
      for(int np=0;np<4;np++) ldsm4(bf[np], bo+(uint32_t)((np*16*PADH)*2+kk*32));
      #pragma unroll
      for(int mt=0;mt<2;mt++)
        #pragma unroll
        for(int np=0;np<4;np++){
          mma16(acc[mt][2*np+0], af[mt], &bf[np][0]);
          mma16(acc[mt][2*np+1], af[mt], &bf[np][2]);
        }
    }
    if(c+2<NC){
      int nb=buf+2; if(nb>=3) nb-=3;
      issue(c+2,nb);
    }
    if(++buf==3) buf=0;
  }

  // ---- epilogue ----
  #pragma unroll
  for(int mt=0;mt<2;mt++){
    int r0=m0+wm*32+mt*16+g4;
    #pragma unroll
    for(int half=0;half<2;half++){
      int r=r0+half*8;
      if(MODE==0){
        int tok; bool valid=true;
        if(z<NE){ tok=g_slot_tok[z*CAP+r]; valid=(tok>=0); }
        else tok=r;
        float mu=0.f, rs=0.f;
        if(valid){ mu=g_mu[tok]; rs=g_rstd[tok]; }
        int strip=n0+wn*64;
        if(strip<2*D){
          __half* hp=g_h+(size_t)(base+r)*D;
          #pragma unroll
          for(int nt=0;nt<8;nt++){
            int d=(strip+nt*8+t4*2)>>1;
            float hv=0.f;
            if(valid){
              float sh=acc[mt][nt][half*2+0]+bias[d];
              float sc=acc[mt][nt][half*2+1]+bias[D+d];
              float xv=p.x[(size_t)tok*D+d];
              hv=(xv-mu)*rs*(1.f+sc)+sh;
            }
            hp[d]=__float2half_rn(hv);
          }
        } else {
          __half* gp=g_gate+(size_t)(base+r)*D;
          #pragma unroll
          for(int nt=0;nt<8;nt++){
            int d0=strip+nt*8+t4*2-2*D;
            float gv0=0.f, gv1=0.f;
            if(valid){
              gv0=acc[mt][nt][half*2+0]+bias[2*D+d0];
              gv1=acc[mt][nt][half*2+1]+bias[2*D+d0+1];
            }
            __half2 hv=__floats2half2_rn(gv0,gv1);
            *(uint32_t*)(gp+d0)=*(uint32_t*)&hv;
          }
        }
      } else if(MODE==1){
        size_t ro=(size_t)(base+r)*ND;
        #pragma unroll
        for(int nt=0;nt<8;nt++){
          int col=n0+wn*64+nt*8+t4*2;
          float v0=gelu_tanh(acc[mt][nt][half*2+0]+bias[col+0]);
          float v1=gelu_tanh(acc[mt][nt][half*2+1]+bias[col+1]);
          __half2 hv=__floats2half2_rn(v0,v1);
          *(uint32_t*)(g_u+ro+col)=*(uint32_t*)&hv;
        }
      } else if(MODE==2){
        const __half* gp=g_gate+(size_t)(base+r)*D;
        int sidx=z*CAP+r;
        int tok=g_slot_tok[sidx];
        if(tok<0) continue;
        float f=g_slot_w[sidx]*p.mask[tok]*(2.f/3.f);
        float* op=p.out+(size_t)tok*D;
        #pragma unroll
        for(int nt=0;nt<8;nt++){
          int col=n0+wn*64+nt*8+t4*2;
          uint32_t gu=*(const uint32_t*)(gp+col);
          float2 gv=__half22float2(*(__half2*)&gu);
          red2(&op[col],
               (acc[mt][nt][half*2+0]+bias[col+0])*gv.x*f,
               (acc[mt][nt][half*2+1]+bias[col+1])*gv.y*f);
        }
      } else {
        // MODE 3: shared-expert store (initializes out)
        const __half* gp=g_gate+(size_t)(base+r)*D;
        float f=p.mask[r]*(1.f/3.f);
        float* op=p.out+(size_t)r*D;
        #pragma unroll
        for(int nt=0;nt<8;nt++){
          int col=n0+wn*64+nt*8+t4*2;
          uint32_t gu=*(const uint32_t*)(gp+col);
          float2 gv=__half22float2(*(__half2*)&gu);
          float2 o;
          o.x=(acc[mt][nt][half*2+0]+bias[col+0])*gv.x*f;
          o.y=(acc[mt][nt][half*2+1]+bias[col+1])*gv.y*f;
          *(float2*)(op+col)=o;
        }
      }
    }
  }
}

extern "C" void kernel_launch(void* const* d_in, const int* in_sizes, int n_in,
                              void* d_out, int out_size){
  P p;
  p.x     =(const float*)d_in[0];
  p.cond  =(const float*)d_in[1];
  p.mask  =(const float*)d_in[2];
  const float* Wg=(const float*)d_in[3];
  p.Wada_s=(const float*)d_in[4];
  p.bada_s=(const float*)d_in[5];
  p.W1_s  =(const float*)d_in[6];
  p.b1_s  =(const float*)d_in[7];
  p.W2_s  =(const float*)d_in[8];
  p.b2_s  =(const float*)d_in[9];
  p.Wada_e=(const float*)d_in[10];
  p.bada_e=(const float*)d_in[11];
  p.W1_e  =(const float*)d_in[12];
  p.b1_e  =(const float*)d_in[13];
  p.W2_e  =(const float*)d_in[14];
  p.b2_e  =(const float*)d_in[15];
  p.out   =(float*)d_out;

  const int SMEM_SZ=6*128*PADH*2;   // 110592 B
  cudaFuncSetAttribute(k_gemm_mma<0>, cudaFuncAttributeMaxDynamicSharedMemorySize, SMEM_SZ);
  cudaFuncSetAttribute(k_gemm_mma<1>, cudaFuncAttributeMaxDynamicSharedMemorySize, SMEM_SZ);
  cudaFuncSetAttribute(k_gemm_mma<2>, cudaFuncAttributeMaxDynamicSharedMemorySize, SMEM_SZ);
  cudaFuncSetAttribute(k_gemm_mma<3>, cudaFuncAttributeMaxDynamicSharedMemorySize, SMEM_SZ);

  // lazily-created side streams/events (host resources only; work is identical each call)
  static cudaStream_t sA=nullptr, sB=nullptr;
  static cudaEvent_t evFork=nullptr, ev1=nullptr, ev2=nullptr;
  static cudaEvent_t evWt0=nullptr, evR=nullptr, evM2s=nullptr, evEnd=nullptr;
  if(!sA){
    cudaStreamCreateWithFlags(&sA, cudaStreamNonBlocking);
    cudaStreamCreateWithFlags(&sB, cudaStreamNonBlocking);
    cudaEventCreateWithFlags(&evFork, cudaEventDisableTiming);
    cudaEventCreateWithFlags(&ev1,    cudaEventDisableTiming);
    cudaEventCreateWithFlags(&ev2,    cudaEventDisableTiming);
    cudaEventCreateWithFlags(&evWt0,  cudaEventDisableTiming);
    cudaEventCreateWithFlags(&evR,    cudaEventDisableTiming);
    cudaEventCreateWithFlags(&evM2s,  cudaEventDisableTiming);
    cudaEventCreateWithFlags(&evEnd,  cudaEventDisableTiming);
  }

  void *pslot=nullptr, *pch=nullptr;
  cudaGetSymbolAddress(&pslot, g_slot_tok);
  cudaGetSymbolAddress(&pch,   g_condh);

  // fork side streams off the origin (capture) stream
  cudaEventRecord(evFork, 0);
  cudaStreamWaitEvent(sA, evFork, 0);
  cudaStreamWaitEvent(sB, evFork, 0);

  // stream A: big weight transposes (consumed by both chains)
  {
    dim3 b(64,4);
    dim3 g1(HID/64, D/64,   NE+1);  k_wt<1><<<g1,b,0,sA>>>(p);
    cudaEventRecord(ev1, sA);
    dim3 g2(D/64,   HID/64, NE+1);  k_wt<2><<<g2,b,0,sA>>>(p);
    cudaEventRecord(ev2, sA);
  }

  // stream B: ROUTED chain prep (router first → evR for shared chain's LN stats)
  {
    cudaMemsetAsync(pslot, 0xFF, sizeof(int)*ROWS_R, sB);
    k_router <<<T/4, 128, 0, sB>>>(p.x, Wg);     // fused router + LN stats
    cudaEventRecord(evR, sB);                     // g_mu/g_rstd ready
    k_hist   <<<NCHUNK, CHUNK, 0, sB>>>();
    k_scan   <<<1, 32, 0, sB>>>();
    k_place  <<<NCHUNK, CHUNK, 0, sB>>>();
  }

  // origin stream: SHARED chain
  {
    size_t n4=(size_t)T*DCND/4;
    k_tohalf<<<(unsigned)((n4+255)/256),256>>>(p.cond,(__half*)pch,n4);
    dim3 b(64,4);
    dim3 ga(AD3/64, DCND/64, NE+1); k_wt<0><<<ga,b>>>(p);
    cudaEventRecord(evWt0, 0);
  }
  cudaStreamWaitEvent(0, evR, 0);               // shared M0 needs g_mu/g_rstd
  dim3 g0s(AD3/128, T/128, 1);  k_gemm_mma<0><<<g0s, 256, SMEM_SZ>>>(p, NE);
  cudaStreamWaitEvent(0, ev1, 0);
  dim3 g1s(HID/128, T/128, 1);  k_gemm_mma<1><<<g1s, 256, SMEM_SZ>>>(p, NE);
  cudaStreamWaitEvent(0, ev2, 0);
  dim3 g2s(D/128,   T/128, 1);  k_gemm_mma<3><<<g2s, 256, SMEM_SZ>>>(p, NE);  // stores out
  cudaEventRecord(evM2s, 0);

  // stream B: ROUTED chain GEMMs (y = CAP/128 = 20 tiles covers capacity bound)
  cudaStreamWaitEvent(sB, evWt0, 0);
  dim3 g0r(AD3/128, MT_R, NE); k_gemm_mma<0><<<g0r, 256, SMEM_SZ, sB>>>(p, 0);
  cudaStreamWaitEvent(sB, ev1, 0);
  dim3 g1r(HID/128, MT_R, NE); k_gemm_mma<1><<<g1r, 256, SMEM_SZ, sB>>>(p, 0);
  cudaStreamWaitEvent(sB, ev2, 0);
  cudaStreamWaitEvent(sB, evM2s, 0);            // red ops must follow shared stores
  dim3 g2r(D/128,   MT_R, NE); k_gemm_mma<2><<<g2r, 256, SMEM_SZ, sB>>>(p, 0);
  cudaEventRecord(evEnd, sB);

  // join routed chain back into origin
  cudaStreamWaitEvent(0, evEnd, 0);
}

// round 17
// speedup vs baseline: 1.0952x; 1.0112x over previous
#include <cuda_runtime.h>
#include <cuda_fp16.h>
#include <math.h>
#include <stdint.h>

#define T 8192
#define D 1024
#define DCND 256
#define NE 8
#define HID 4096
#define CAP 2560
#define NTOK (T*2)
#define ROWS_R (NE*CAP)
#define ROWS_ALL (ROWS_R+T)
#define AD3 3072
#define NCHUNK 64
#define CHUNK 256
#define KC 64                 // K halves per chunk = 128B/row
#define PADH 72               // halves per smem row (64 + 8 pad) = 144B
#define MT_R (CAP/128)        // 20 m-tiles cover capacity-bounded routed experts

// ---------------- scratch (device globals; no allocations) ----------------
__device__ int   g_tope[NTOK];
__device__ float g_topw[NTOK];
__device__ int   g_hist[NCHUNK*NE];
__device__ int   g_coff[NCHUNK*NE];
__device__ int   g_tpe[NE];
__device__ int   g_starts[NE];
__device__ int   g_ne[NE];
__device__ int   g_slot_tok[ROWS_R];
__device__ float g_slot_w[ROWS_R];
__device__ float g_mu[T];
__device__ float g_rstd[T];
__device__ __half g_gate[(size_t)ROWS_ALL*D];    // adaLN gate (fp16)
__device__ __half g_h[(size_t)ROWS_ALL*D];       // modulated LN input (fp16)
__device__ __half g_u[(size_t)ROWS_ALL*HID];     // gelu(h@W1+b1) (fp16)
__device__ __half g_condh[(size_t)T*DCND];       // fp16 cond
// transposed [z][N][K] fp16 weights (Wada column-permuted: pairs (shift_d,scale_d), then gate)
__device__ __half g_wadat[(size_t)(NE+1)*AD3*DCND];
__device__ __half g_w1t[(size_t)(NE+1)*HID*D];
__device__ __half g_w2t[(size_t)(NE+1)*D*HID];

struct P {
  const float *x,*cond,*mask;
  const float *Wada_s,*bada_s,*W1_s,*b1_s,*W2_s,*b2_s;
  const float *Wada_e,*bada_e,*W1_e,*b1_e,*W2_e,*b2_e;
  float *out;
};

// ---------------- helpers ----------------
__device__ __forceinline__ uint32_t s2u(const void* p){
  uint32_t a;
  asm("{ .reg .u64 t; cvta.to.shared.u64 t, %1; cvt.u32.u64 %0, t; }" : "=r"(a) : "l"(p));
  return a;
}
__device__ __forceinline__ void cp16(uint32_t d, const void* s, uint32_t sz){
  asm volatile("cp.async.cg.shared.global [%0], [%1], 16, %2;" :: "r"(d),"l"(s),"r"(sz) : "memory");
}
__device__ __forceinline__ void mma16(float* c, const uint32_t* a, const uint32_t* b){
  asm volatile("mma.sync.aligned.m16n8k16.row.col.f32.f16.f16.f32 "
    "{%0,%1,%2,%3}, {%4,%5,%6,%7}, {%8,%9}, {%0,%1,%2,%3};"
    : "+f"(c[0]),"+f"(c[1]),"+f"(c[2]),"+f"(c[3])
    : "r"(a[0]),"r"(a[1]),"r"(a[2]),"r"(a[3]), "r"(b[0]),"r"(b[1]));
}
__device__ __forceinline__ void ldsm4(uint32_t* r, uint32_t a){
  asm volatile("ldmatrix.sync.aligned.m8n8.x4.shared.b16 {%0,%1,%2,%3}, [%4];"
    : "=r"(r[0]),"=r"(r[1]),"=r"(r[2]),"=r"(r[3]) : "r"(a));
}
__device__ __forceinline__ void red2(float* a, float v0, float v1){
  asm volatile("red.global.add.v2.f32 [%0], {%1, %2};" :: "l"(a), "f"(v0), "f"(v1) : "memory");
}

// ---------------- f32 -> f16 copy (cond) ----------------
__global__ void k_tohalf(const float* __restrict__ s, __half* __restrict__ d, size_t n4){
  size_t i=(size_t)blockIdx.x*blockDim.x+threadIdx.x;
  if(i>=n4) return;
  float4 v=((const float4*)s)[i];
  __half2 lo=__floats2half2_rn(v.x,v.y);
  __half2 hi=__floats2half2_rn(v.z,v.w);
  uint2 o; o.x=*(uint32_t*)&lo; o.y=*(uint32_t*)&hi;
  ((uint2*)d)[i]=o;
}

// ---------------- weight transpose [K,N]->[N,K] fp16, 64x64 tiles ----------------
template<int MODE>
__global__ void k_wt(P p){
  constexpr int KD=(MODE==0)?DCND:(MODE==1)?D:HID;
  constexpr int ND=(MODE==0)?AD3:(MODE==1)?HID:D;
  int z=blockIdx.z;
  const float* W;
  if(MODE==0) W=(z<NE)? p.Wada_e+(size_t)z*KD*ND : p.Wada_s;
  else if(MODE==1) W=(z<NE)? p.W1_e+(size_t)z*KD*ND : p.W1_s;
  else W=(z<NE)? p.W2_e+(size_t)z*KD*ND : p.W2_s;
  __half* Wt=((MODE==0)? g_wadat : (MODE==1)? g_w1t : g_w2t)+(size_t)z*KD*ND;
  __shared__ float t[64][65];
  int n0=blockIdx.x*64, k0=blockIdx.y*64;
  int tx=threadIdx.x, ty=threadIdx.y;        // tx 0..63, ty 0..3
  int n=n0+tx;
  int srcn=n;
  if(MODE==0 && n<2*D) srcn=(n&1)? D+(n>>1) : (n>>1);   // interleave shift/scale
  #pragma unroll
  for(int r=0;r<16;r++){
    int kr=ty+4*r;
    t[kr][tx]=W[(size_t)(k0+kr)*ND+srcn];
  }
  __syncthreads();
  #pragma unroll
  for(int r=0;r<16;r++){
    int nr=ty+4*r;
    Wt[(size_t)(n0+nr)*KD+k0+tx]=__float2half_rn(t[tx][nr]);
  }
}

// ---------------- router + LN stats fused: warp/token ----------------
__global__ void k_router(const float* __restrict__ x, const float* __restrict__ Wg){
  int w=(blockIdx.x*blockDim.x+threadIdx.x)>>5;
  int lane=threadIdx.x&31;
  if(w>=T) return;
  const float* xr=x+(size_t)w*D;
  float a[7]={0.f,0.f,0.f,0.f,0.f,0.f,0.f};
  float s=0.f,s2=0.f;
  for(int k=lane;k<D;k+=32){
    float xv=xr[k];
    s+=xv; s2+=xv*xv;
    #pragma unroll
    for(int j=0;j<7;j++) a[j]+=xv*Wg[k*7+j];
  }
  #pragma unroll
  for(int j=0;j<7;j++)
    for(int o=16;o;o>>=1) a[j]+=__shfl_xor_sync(0xffffffffu,a[j],o);
  for(int o=16;o;o>>=1){
    s+=__shfl_xor_sync(0xffffffffu,s,o);
    s2+=__shfl_xor_sync(0xffffffffu,s2,o);
  }
  if(lane==0){
    int j0=0;
    #pragma unroll
    for(int j=1;j<7;j++) if(a[j]>a[j0]) j0=j;
    int j1=-1;
    #pragma unroll
    for(int j=0;j<7;j++){ if(j==j0) continue; if(j1<0||a[j]>a[j1]) j1=j; }
    float e1=expf(a[j1]-a[j0]);
    float inv=1.f/(1.f+e1);
    g_tope[2*w]=j0;   g_topw[2*w]=inv;
    g_tope[2*w+1]=j1; g_topw[2*w+1]=e1*inv;
    float mu=s*(1.f/(float)D);
    float var=s2*(1.f/(float)D)-mu*mu;
    g_mu[w]=mu;
    g_rstd[w]=rsqrtf(var+1e-5f);
  }
}

// ---------------- stable counting sort by expert ----------------
__global__ void k_hist(){
  __shared__ int cnt[NE];
  int tid=threadIdx.x;
  if(tid<NE) cnt[tid]=0;
  __syncthreads();
  atomicAdd(&cnt[g_tope[blockIdx.x*CHUNK+tid]],1);
  __syncthreads();
  if(tid<NE) g_hist[blockIdx.x*NE+tid]=cnt[tid];
}
__global__ void k_scan(){
  int tid=threadIdx.x;
  __shared__ int tpe[NE], st[NE];
  if(tid<NE){
    int s=0;
    for(int c=0;c<NCHUNK;c++) s+=g_hist[c*NE+tid];
    tpe[tid]=s; g_tpe[tid]=s; g_ne[tid]=s<CAP?s:CAP;
  }
  __syncthreads();
  if(tid==0){
    int cum=0;
    for(int e=0;e<NE;e++){ st[e]=cum; g_starts[e]=cum; cum+=tpe[e]; }
  }
  __syncthreads();
  if(tid<NE){
    int run=st[tid];
    for(int c=0;c<NCHUNK;c++){ g_coff[c*NE+tid]=run; run+=g_hist[c*NE+tid]; }
  }
}
__global__ void k_place(){
  __shared__ int se[CHUNK];
  int tid=threadIdx.x;
  int g=blockIdx.x*CHUNK+tid;
  int e=g_tope[g];
  se[tid]=e;
  __syncthreads();
  int rank=0;
  for(int j=0;j<tid;j++) rank += (se[j]==e);
  int pos=g_coff[blockIdx.x*NE+e]+rank;
  int slot=pos-g_starts[e];
  if(slot<CAP){
    g_slot_tok[e*CAP+slot]=g>>1;
    g_slot_w[e*CAP+slot]=g_topw[g];
  }
}

// fast gelu-tanh: tanh(y) = 1 - 2/(1+e^{2y}) via ex2.approx + rcp.approx (~1e-6 rel err)
__device__ __forceinline__ float gelu_tanh(float v){
  const float c=0.7978845608028654f;
  float y=c*(v+0.044715f*v*v*v);
  float e; asm("ex2.approx.f32 %0, %1;" : "=f"(e) : "f"(2.885390081777927f*y));
  float r; asm("rcp.approx.f32 %0, %1;" : "=f"(r) : "f"(e+1.f));
  float th=1.f-2.f*r;
  return 0.5f*v*(1.f+th);
}

// ---------------- fp16 mma.sync GEMM, 128x128 tile, 256 thr, 3-stage cp.async ----------------
// MODE 0: ada(permuted) -> fused LN-modulate epilogue -> g_h, g_gate
// MODE 1: u = f16(gelu(g_h @ W1 + b1))
// MODE 2: y -> routed: gate*mask*w*2/3 red.v2 out
// MODE 3: y -> shared: gate*mask*1/3 red.v2 out (out pre-zeroed)
template<int MODE>
__global__ void __launch_bounds__(256,2) k_gemm_mma(P p, int z0){
  constexpr int KD=(MODE==0)?DCND:(MODE==1)?D:HID;
  constexpr int ND=(MODE==0)?AD3:(MODE==1)?HID:D;
  constexpr int NC=KD/KC;
  constexpr uint32_t BUF=128*PADH*2;    // 18432 B per stage per operand

  int z=blockIdx.z+z0;
  int Mz=(z<NE)? g_ne[z] : T;
  int m0=blockIdx.y*128;
  if(m0>=Mz) return;
  int n0=blockIdx.x*128;
  int base=(z<NE)? z*CAP : ROWS_R;

  extern __shared__ __half smh[];
  uint32_t sa=s2u(smh);        // A: 3 stages
  uint32_t sb=sa+3*BUF;        // B: 3 stages

  int tid=threadIdx.x, warp=tid>>5, lane=tid&31;
  int wm=warp>>1, wn=warp&1;
  int g4=lane>>2, t4=lane&3;
  int tsel=lane>>3, tr=lane&7;

  const __half* Wt=((MODE==0)? g_wadat : (MODE==1)? g_w1t : g_w2t)+(size_t)z*(size_t)KD*ND;
  const float* bias;
  if(MODE==0) bias=(z<NE)? p.bada_e+z*AD3 : p.bada_s;
  else if(MODE==1) bias=(z<NE)? p.b1_e+z*HID : p.b1_s;
  else bias=(z<NE)? p.b2_e+z*D : p.b2_s;

  // loaders: thread owns row (tid>>1), half-row segment (tid&1)
  int lrow=tid>>1, lseg=tid&1;
  const __half* pA;
  uint32_t asz=16;
  if(MODE==0){
    int tok=(z<NE)? g_slot_tok[z*CAP+m0+lrow] : (m0+lrow);
    if(tok<0){ tok=0; asz=0; }
    pA=g_condh+(size_t)tok*DCND+lseg*32;
  } else {
    const __half* Ab=(MODE==1)? g_h : g_u;
    pA=Ab+(size_t)(base+m0+lrow)*KD+lseg*32;
  }
  const __half* pB=Wt+(size_t)(n0+lrow)*KD+lseg*32;

  uint32_t da0=sa+(uint32_t)(lrow*PADH+lseg*32)*2;
  uint32_t db0=sb+(uint32_t)(lrow*PADH+lseg*32)*2;

  uint32_t abase=sa+(uint32_t)(((wm*32+(tsel&1)*8+tr)*PADH+(tsel>>1)*8)*2);
  uint32_t bbase=sb+(uint32_t)(((wn*64+(tsel>>1)*8+tr)*PADH+(tsel&1)*8)*2);

  float acc[2][8][4];
  #pragma unroll
  for(int mt=0;mt<2;mt++)
    #pragma unroll
    for(int nt=0;nt<8;nt++)
      #pragma unroll
      for(int r=0;r<4;r++) acc[mt][nt][r]=0.f;

  auto issue=[&](int c,int buf){
    uint32_t da=da0+buf*BUF;
    const __half* srcA=pA+(size_t)c*KC;
    #pragma unroll
    for(int i=0;i<4;i++) cp16(da+i*16, srcA+i*8, asz);
    uint32_t db=db0+buf*BUF;
    const __half* srcB=pB+(size_t)c*KC;
    #pragma unroll
    for(int i=0;i<4;i++) cp16(db+i*16, srcB+i*8, 16u);
    asm volatile("cp.async.commit_group;" ::: "memory");
  };

  issue(0,0);
  if(NC>1) issue(1,1);
  int buf=0;
  for(int c=0;c<NC;c++){
    if(c+1<NC) asm volatile("cp.async.wait_group 1;" ::: "memory");
    else       asm volatile("cp.async.wait_group 0;" ::: "memory");
    __syncthreads();
    uint32_t ao=abase+buf*BUF;
    uint32_t bo=bbase+buf*BUF;
    #pragma unroll
    for(int kk=0;kk<4;kk++){                 // 4 x K16 per chunk
      uint32_t af[2][4], bf[4][4];
      #pragma unroll
      for(int mt=0;mt<2;mt++) ldsm4(af[mt], ao+(uint32_t)((mt*16*PADH)*2+kk*32));
      #pragma unroll
      for(int np=0;np<4;np++) ldsm4(bf[np], bo+(uint32_t)((np*16*PADH)*2+kk*32));
      #pragma unroll
      for(int mt=0;mt<2;mt++)
        #pragma unroll
        for(int np=0;np<4;np++){
          mma16(acc[mt][2*np+0], af[mt], &bf[np][0]);
          mma16(acc[mt][2*np+1], af[mt], &bf[np][2]);
        }
    }
    if(c+2<NC){
      int nb=buf+2; if(nb>=3) nb-=3;
      issue(c+2,nb);
    }
    if(++buf==3) buf=0;
  }

  // ---- epilogue ----
  #pragma unroll
  for(int mt=0;mt<2;mt++){
    int r0=m0+wm*32+mt*16+g4;
    #pragma unroll
    for(int half=0;half<2;half++){
      int r=r0+half*8;
      if(MODE==0){
        int tok; bool valid=true;
        if(z<NE){ tok=g_slot_tok[z*CAP+r]; valid=(tok>=0); }
        else tok=r;
        float mu=0.f, rs=0.f;
        if(valid){ mu=g_mu[tok]; rs=g_rstd[tok]; }
        int strip=n0+wn*64;
        if(strip<2*D){
          __half* hp=g_h+(size_t)(base+r)*D;
          #pragma unroll
          for(int nt=0;nt<8;nt++){
            int d=(strip+nt*8+t4*2)>>1;
            float hv=0.f;
            if(valid){
              float sh=acc[mt][nt][half*2+0]+bias[d];
              float sc=acc[mt][nt][half*2+1]+bias[D+d];
              float xv=p.x[(size_t)tok*D+d];
              hv=(xv-mu)*rs*(1.f+sc)+sh;
            }
            hp[d]=__float2half_rn(hv);
          }
        } else {
          __half* gp=g_gate+(size_t)(base+r)*D;
          #pragma unroll
          for(int nt=0;nt<8;nt++){
            int d0=strip+nt*8+t4*2-2*D;
            float gv0=0.f, gv1=0.f;
            if(valid){
              gv0=acc[mt][nt][half*2+0]+bias[2*D+d0];
              gv1=acc[mt][nt][half*2+1]+bias[2*D+d0+1];
            }
            __half2 hv=__floats2half2_rn(gv0,gv1);
            *(uint32_t*)(gp+d0)=*(uint32_t*)&hv;
          }
        }
      } else if(MODE==1){
        size_t ro=(size_t)(base+r)*ND;
        #pragma unroll
        for(int nt=0;nt<8;nt++){
          int col=n0+wn*64+nt*8+t4*2;
          float v0=gelu_tanh(acc[mt][nt][half*2+0]+bias[col+0]);
          float v1=gelu_tanh(acc[mt][nt][half*2+1]+bias[col+1]);
          __half2 hv=__floats2half2_rn(v0,v1);
          *(uint32_t*)(g_u+ro+col)=*(uint32_t*)&hv;
        }
      } else if(MODE==2){
        const __half* gp=g_gate+(size_t)(base+r)*D;
        int sidx=z*CAP+r;
        int tok=g_slot_tok[sidx];
        if(tok<0) continue;
        float f=g_slot_w[sidx]*p.mask[tok]*(2.f/3.f);
        float* op=p.out+(size_t)tok*D;
        #pragma unroll
        for(int nt=0;nt<8;nt++){
          int col=n0+wn*64+nt*8+t4*2;
          uint32_t gu=*(const uint32_t*)(gp+col);
          float2 gv=__half22float2(*(__half2*)&gu);
          red2(&op[col],
               (acc[mt][nt][half*2+0]+bias[col+0])*gv.x*f,
               (acc[mt][nt][half*2+1]+bias[col+1])*gv.y*f);
        }
      } else {
        // MODE 3: shared-expert contribution via red (out pre-zeroed)
        const __half* gp=g_gate+(size_t)(base+r)*D;
        float f=p.mask[r]*(1.f/3.f);
        float* op=p.out+(size_t)r*D;
        #pragma unroll
        for(int nt=0;nt<8;nt++){
          int col=n0+wn*64+nt*8+t4*2;
          uint32_t gu=*(const uint32_t*)(gp+col);
          float2 gv=__half22float2(*(__half2*)&gu);
          red2(&op[col],
               (acc[mt][nt][half*2+0]+bias[col+0])*gv.x*f,
               (acc[mt][nt][half*2+1]+bias[col+1])*gv.y*f);
        }
      }
    }
  }
}

extern "C" void kernel_launch(void* const* d_in, const int* in_sizes, int n_in,
                              void* d_out, int out_size){
  P p;
  p.x     =(const float*)d_in[0];
  p.cond  =(const float*)d_in[1];
  p.mask  =(const float*)d_in[2];
  const float* Wg=(const float*)d_in[3];
  p.Wada_s=(const float*)d_in[4];
  p.bada_s=(const float*)d_in[5];
  p.W1_s  =(const float*)d_in[6];
  p.b1_s  =(const float*)d_in[7];
  p.W2_s  =(const float*)d_in[8];
  p.b2_s  =(const float*)d_in[9];
  p.Wada_e=(const float*)d_in[10];
  p.bada_e=(const float*)d_in[11];
  p.W1_e  =(const float*)d_in[12];
  p.b1_e  =(const float*)d_in[13];
  p.W2_e  =(const float*)d_in[14];
  p.b2_e  =(const float*)d_in[15];
  p.out   =(float*)d_out;

  const int SMEM_SZ=6*128*PADH*2;   // 110592 B
  cudaFuncSetAttribute(k_gemm_mma<0>, cudaFuncAttributeMaxDynamicSharedMemorySize, SMEM_SZ);
  cudaFuncSetAttribute(k_gemm_mma<1>, cudaFuncAttributeMaxDynamicSharedMemorySize, SMEM_SZ);
  cudaFuncSetAttribute(k_gemm_mma<2>, cudaFuncAttributeMaxDynamicSharedMemorySize, SMEM_SZ);
  cudaFuncSetAttribute(k_gemm_mma<3>, cudaFuncAttributeMaxDynamicSharedMemorySize, SMEM_SZ);

  // lazily-created side streams/events (host resources only; work is identical each call)
  static cudaStream_t sA=nullptr, sB=nullptr;
  static cudaEvent_t evFork=nullptr, ev1=nullptr, ev2=nullptr;
  static cudaEvent_t evWt0=nullptr, evR=nullptr, evZ=nullptr, evEnd=nullptr;
  if(!sA){
    cudaStreamCreateWithFlags(&sA, cudaStreamNonBlocking);
    cudaStreamCreateWithFlags(&sB, cudaStreamNonBlocking);
    cudaEventCreateWithFlags(&evFork, cudaEventDisableTiming);
    cudaEventCreateWithFlags(&ev1,    cudaEventDisableTiming);
    cudaEventCreateWithFlags(&ev2,    cudaEventDisableTiming);
    cudaEventCreateWithFlags(&evWt0,  cudaEventDisableTiming);
    cudaEventCreateWithFlags(&evR,    cudaEventDisableTiming);
    cudaEventCreateWithFlags(&evZ,    cudaEventDisableTiming);
    cudaEventCreateWithFlags(&evEnd,  cudaEventDisableTiming);
  }

  void *pslot=nullptr, *pch=nullptr;
  cudaGetSymbolAddress(&pslot, g_slot_tok);
  cudaGetSymbolAddress(&pch,   g_condh);

  // fork side streams off the origin (capture) stream
  cudaEventRecord(evFork, 0);
  cudaStreamWaitEvent(sA, evFork, 0);
  cudaStreamWaitEvent(sB, evFork, 0);

  // stream A: zero out (hidden under transposes), then big weight transposes
  {
    cudaMemsetAsync(p.out, 0, sizeof(float)*(size_t)T*D, sA);
    cudaEventRecord(evZ, sA);
    dim3 b(64,4);
    dim3 g1(HID/64, D/64,   NE+1);  k_wt<1><<<g1,b,0,sA>>>(p);
    cudaEventRecord(ev1, sA);
    dim3 g2(D/64,   HID/64, NE+1);  k_wt<2><<<g2,b,0,sA>>>(p);
    cudaEventRecord(ev2, sA);
  }

  // stream B: ROUTED chain prep (router first → evR for shared chain's LN stats)
  {
    cudaMemsetAsync(pslot, 0xFF, sizeof(int)*ROWS_R, sB);
    k_router <<<T/4, 128, 0, sB>>>(p.x, Wg);     // fused router + LN stats
    cudaEventRecord(evR, sB);                     // g_mu/g_rstd ready
    k_hist   <<<NCHUNK, CHUNK, 0, sB>>>();
    k_scan   <<<1, 32, 0, sB>>>();
    k_place  <<<NCHUNK, CHUNK, 0, sB>>>();
  }

  // origin stream: SHARED chain
  {
    size_t n4=(size_t)T*DCND/4;
    k_tohalf<<<(unsigned)((n4+255)/256),256>>>(p.cond,(__half*)pch,n4);
    dim3 b(64,4);
    dim3 ga(AD3/64, DCND/64, NE+1); k_wt<0><<<ga,b>>>(p);
    cudaEventRecord(evWt0, 0);
  }
  cudaStreamWaitEvent(0, evR, 0);               // shared M0 needs g_mu/g_rstd
  dim3 g0s(AD3/128, T/128, 1);  k_gemm_mma<0><<<g0s, 256, SMEM_SZ>>>(p, NE);
  cudaStreamWaitEvent(0, ev1, 0);
  dim3 g1s(HID/128, T/128, 1);  k_gemm_mma<1><<<g1s, 256, SMEM_SZ>>>(p, NE);
  cudaStreamWaitEvent(0, ev2, 0);
  cudaStreamWaitEvent(0, evZ, 0);               // out must be zeroed before red
  dim3 g2s(D/128,   T/128, 1);  k_gemm_mma<3><<<g2s, 256, SMEM_SZ>>>(p, NE);
  // stream B: ROUTED chain GEMMs (no dependency on shared M3 anymore)
  cudaStreamWaitEvent(sB, evWt0, 0);
  dim3 g0r(AD3/128, MT_R, NE); k_gemm_mma<0><<<g0r, 256, SMEM_SZ, sB>>>(p, 0);
  cudaStreamWaitEvent(sB, ev1, 0);
  dim3 g1r(HID/128, MT_R, NE); k_gemm_mma<1><<<g1r, 256, SMEM_SZ, sB>>>(p, 0);
  cudaStreamWaitEvent(sB, ev2, 0);
  cudaStreamWaitEvent(sB, evZ, 0);              // out must be zeroed before red
  dim3 g2r(D/128,   MT_R, NE); k_gemm_mma<2><<<g2r, 256, SMEM_SZ, sB>>>(p, 0);
  cudaEventRecord(evEnd, sB);

  // join routed chain back into origin
  cudaStreamWaitEvent(0, evEnd, 0);
}